// round 2
// baseline (speedup 1.0000x reference)
#include <cuda_runtime.h>
#include <math.h>

#define D_EMBED 2048
#define SEQ     2048
#define NH      32
#define HD      64
#define D3      (3 * D_EMBED)       // 6144
#define QK_SCALE 0.125f             // 64^-0.5

// Scratch (allocation-free rule): qkv buffer + attention output buffer
__device__ float g_qkv[SEQ * D3];        // [2048, 6144]  ~50 MB
__device__ float g_attn[SEQ * D_EMBED];  // [2048, 2048]  ~16 MB

// ---------------------------------------------------------------------------
// NT GEMM with bias: C[M,N] = A[M,K] * B[N,K]^T + bias[N]
// BM=BN=128, BK=16, 256 threads, 8x8 accum per thread.
// ---------------------------------------------------------------------------
__global__ __launch_bounds__(256)
void gemm_nt_bias(const float* __restrict__ A, const float* __restrict__ B,
                  const float* __restrict__ bias, float* __restrict__ C,
                  int N, int K)
{
    __shared__ float As[16][128];   // [k][m]
    __shared__ float Bs[16][128];   // [k][n]

    const int tid = threadIdx.x;
    const int ty = tid >> 4;        // 0..15
    const int tx = tid & 15;        // 0..15
    const int m0 = blockIdx.y * 128;
    const int n0 = blockIdx.x * 128;

    float acc[8][8];
#pragma unroll
    for (int i = 0; i < 8; i++)
#pragma unroll
        for (int j = 0; j < 8; j++) acc[i][j] = 0.f;

    for (int k0 = 0; k0 < K; k0 += 16) {
        // 128x16 tiles: 512 float4 chunks, 2 per thread, stored transposed
#pragma unroll
        for (int j = 0; j < 2; j++) {
            int c   = tid + j * 256;          // 0..511
            int row = c >> 2;                 // 0..127
            int kq  = (c & 3) << 2;           // 0,4,8,12
            float4 va = *(const float4*)(A + (size_t)(m0 + row) * K + k0 + kq);
            As[kq + 0][row] = va.x; As[kq + 1][row] = va.y;
            As[kq + 2][row] = va.z; As[kq + 3][row] = va.w;
            float4 vb = *(const float4*)(B + (size_t)(n0 + row) * K + k0 + kq);
            Bs[kq + 0][row] = vb.x; Bs[kq + 1][row] = vb.y;
            Bs[kq + 2][row] = vb.z; Bs[kq + 3][row] = vb.w;
        }
        __syncthreads();

#pragma unroll
        for (int kk = 0; kk < 16; kk++) {
            float a[8], b[8];
            *(float4*)(a)     = *(const float4*)&As[kk][ty * 8];
            *(float4*)(a + 4) = *(const float4*)&As[kk][ty * 8 + 4];
            *(float4*)(b)     = *(const float4*)&Bs[kk][tx * 8];
            *(float4*)(b + 4) = *(const float4*)&Bs[kk][tx * 8 + 4];
#pragma unroll
            for (int i = 0; i < 8; i++)
#pragma unroll
                for (int j = 0; j < 8; j++)
                    acc[i][j] = fmaf(a[i], b[j], acc[i][j]);
        }
        __syncthreads();
    }

    float bv[8];
#pragma unroll
    for (int j = 0; j < 8; j++) bv[j] = bias[n0 + tx * 8 + j];

#pragma unroll
    for (int i = 0; i < 8; i++) {
        float* crow = C + (size_t)(m0 + ty * 8 + i) * N + n0 + tx * 8;
        float4 o0 = make_float4(acc[i][0] + bv[0], acc[i][1] + bv[1],
                                acc[i][2] + bv[2], acc[i][3] + bv[3]);
        float4 o1 = make_float4(acc[i][4] + bv[4], acc[i][5] + bv[5],
                                acc[i][6] + bv[6], acc[i][7] + bv[7]);
        *(float4*)(crow)     = o0;
        *(float4*)(crow + 4) = o1;
    }
}

// ---------------------------------------------------------------------------
// Causal flash attention, fp32, dynamic smem (66.5 KB > 48 KB static cap).
// One CTA per (query block of 64, head). Q,K stored d-major in smem
// (conflict-free fragment reads), V row-major, Ss padded to stride 65.
// O accumulators live in registers (4x4/thread).
// ---------------------------------------------------------------------------
// dynamic smem layout (floats):
#define SM_QST   0                        // [64][64]
#define SM_KST   (SM_QST + 64 * 64)       // [64][64]
#define SM_VS    (SM_KST + 64 * 64)       // [64][64]
#define SM_SS    (SM_VS  + 64 * 64)       // [64][65]
#define SM_MROW  (SM_SS  + 64 * 65)       // [64]
#define SM_LROW  (SM_MROW + 64)           // [64]
#define SM_AROW  (SM_LROW + 64)           // [64]
#define SM_TOTAL (SM_AROW + 64)           // floats
#define FLASH_SMEM_BYTES (SM_TOTAL * 4)   // 66816 B

__global__ __launch_bounds__(256)
void flash_attn(const float* __restrict__ qkv, float* __restrict__ attn)
{
    extern __shared__ float sm[];
    float (*QsT)[64] = (float (*)[64])(sm + SM_QST);
    float (*KsT)[64] = (float (*)[64])(sm + SM_KST);
    float (*Vs)[64]  = (float (*)[64])(sm + SM_VS);
    float (*Ss)[65]  = (float (*)[65])(sm + SM_SS);
    float* mrow = sm + SM_MROW;
    float* lrow = sm + SM_LROW;
    float* arow = sm + SM_AROW;

    const int tid = threadIdx.x;
    const int ty = tid >> 4;        // 0..15
    const int tx = tid & 15;        // 0..15
    const int r0 = ty * 4;          // query rows r0..r0+3
    const int c0 = tx * 4;          // key cols / hd cols c0..c0+3
    const int qb = blockIdx.x;      // 0..31
    const int h  = blockIdx.y;      // 0..31
    const int qbase = qb * 64;

    // Load Q tile (transposed, scaled)
#pragma unroll
    for (int j = 0; j < 4; j++) {
        int c  = tid + j * 256;     // 0..1023
        int r  = c >> 4;            // 0..63
        int d4 = (c & 15) << 2;     // 0..60
        float4 v = *(const float4*)(qkv + (size_t)(qbase + r) * D3 + h * HD + d4);
        QsT[d4 + 0][r] = v.x * QK_SCALE; QsT[d4 + 1][r] = v.y * QK_SCALE;
        QsT[d4 + 2][r] = v.z * QK_SCALE; QsT[d4 + 3][r] = v.w * QK_SCALE;
    }
    if (tid < 64) { mrow[tid] = -1e30f; lrow[tid] = 0.f; }

    float o[4][4];
#pragma unroll
    for (int i = 0; i < 4; i++)
#pragma unroll
        for (int j = 0; j < 4; j++) o[i][j] = 0.f;

    for (int kt = 0; kt <= qb; kt++) {
        __syncthreads();   // prev PV done; Q ready on first pass
        // Load K (transposed) + V tiles
#pragma unroll
        for (int j = 0; j < 4; j++) {
            int c  = tid + j * 256;
            int r  = c >> 4;
            int d4 = (c & 15) << 2;
            size_t base = (size_t)(kt * 64 + r) * D3 + h * HD + d4;
            float4 kv = *(const float4*)(qkv + D_EMBED + base);
            KsT[d4 + 0][r] = kv.x; KsT[d4 + 1][r] = kv.y;
            KsT[d4 + 2][r] = kv.z; KsT[d4 + 3][r] = kv.w;
            float4 vv = *(const float4*)(qkv + 2 * D_EMBED + base);
            *(float4*)&Vs[r][d4] = vv;
        }
        __syncthreads();

        // S = Q K^T (4x4 per thread)
        float s[4][4];
#pragma unroll
        for (int i = 0; i < 4; i++)
#pragma unroll
            for (int j = 0; j < 4; j++) s[i][j] = 0.f;
#pragma unroll 16
        for (int d = 0; d < 64; d++) {
            float4 qa = *(const float4*)&QsT[d][r0];
            float4 kb = *(const float4*)&KsT[d][c0];
            float qv[4] = {qa.x, qa.y, qa.z, qa.w};
            float kv[4] = {kb.x, kb.y, kb.z, kb.w};
#pragma unroll
            for (int i = 0; i < 4; i++)
#pragma unroll
                for (int j = 0; j < 4; j++)
                    s[i][j] = fmaf(qv[i], kv[j], s[i][j]);
        }

        // Causal mask (only diagonal tile) + spill raw scores for rowmax
        const bool diag = (kt == qb);
#pragma unroll
        for (int i = 0; i < 4; i++)
#pragma unroll
            for (int j = 0; j < 4; j++) {
                if (diag && (c0 + j) > (r0 + i)) s[i][j] = -1e30f;
                Ss[r0 + i][c0 + j] = s[i][j];
            }
        __syncthreads();

        // Row max + alpha
        if (tid < 64) {
            float m_old = mrow[tid];
            float mx = m_old;
            const float* srow = &Ss[tid][0];
#pragma unroll 16
            for (int c = 0; c < 64; c++) mx = fmaxf(mx, srow[c]);
            mrow[tid] = mx;
            arow[tid] = __expf(m_old - mx);
        }
        __syncthreads();

        // Exponentiate (from registers), rescale O
#pragma unroll
        for (int i = 0; i < 4; i++) {
            float mi = mrow[r0 + i];
            float ai = arow[r0 + i];
#pragma unroll
            for (int j = 0; j < 4; j++) {
                float p = __expf(s[i][j] - mi);
                Ss[r0 + i][c0 + j] = p;
                o[i][j] *= ai;
            }
        }
        __syncthreads();

        // Row sum (64 threads) runs alongside PV (reads only)
        if (tid < 64) {
            float sum = 0.f;
            const float* srow = &Ss[tid][0];
#pragma unroll 16
            for (int c = 0; c < 64; c++) sum += srow[c];
            lrow[tid] = lrow[tid] * arow[tid] + sum;
        }

        // O += P V
#pragma unroll 8
        for (int k = 0; k < 64; k++) {
            float4 vv = *(const float4*)&Vs[k][c0];
            float p0 = Ss[r0 + 0][k], p1 = Ss[r0 + 1][k];
            float p2 = Ss[r0 + 2][k], p3 = Ss[r0 + 3][k];
            o[0][0] = fmaf(p0, vv.x, o[0][0]); o[0][1] = fmaf(p0, vv.y, o[0][1]);
            o[0][2] = fmaf(p0, vv.z, o[0][2]); o[0][3] = fmaf(p0, vv.w, o[0][3]);
            o[1][0] = fmaf(p1, vv.x, o[1][0]); o[1][1] = fmaf(p1, vv.y, o[1][1]);
            o[1][2] = fmaf(p1, vv.z, o[1][2]); o[1][3] = fmaf(p1, vv.w, o[1][3]);
            o[2][0] = fmaf(p2, vv.x, o[2][0]); o[2][1] = fmaf(p2, vv.y, o[2][1]);
            o[2][2] = fmaf(p2, vv.z, o[2][2]); o[2][3] = fmaf(p2, vv.w, o[2][3]);
            o[3][0] = fmaf(p3, vv.x, o[3][0]); o[3][1] = fmaf(p3, vv.y, o[3][1]);
            o[3][2] = fmaf(p3, vv.z, o[3][2]); o[3][3] = fmaf(p3, vv.w, o[3][3]);
        }
    }
    __syncthreads();

    // Normalize + write: attn[s, h*64 + d]
#pragma unroll
    for (int i = 0; i < 4; i++) {
        float linv = 1.f / lrow[r0 + i];
        float4 ov = make_float4(o[i][0] * linv, o[i][1] * linv,
                                o[i][2] * linv, o[i][3] * linv);
        *(float4*)(attn + (size_t)(qbase + r0 + i) * D_EMBED + h * HD + c0) = ov;
    }
}

// ---------------------------------------------------------------------------
extern "C" void kernel_launch(void* const* d_in, const int* in_sizes, int n_in,
                              void* d_out, int out_size)
{
    const float* hidden = (const float*)d_in[0];   // [1,2048,2048]
    const float* w_qkv  = (const float*)d_in[1];   // [6144,2048]
    const float* b_qkv  = (const float*)d_in[2];   // [6144]
    const float* w_out  = (const float*)d_in[3];   // [2048,2048]
    const float* b_out  = (const float*)d_in[4];   // [2048]
    float* out = (float*)d_out;                    // [1,2048,2048]

    float* qkv;  cudaGetSymbolAddress((void**)&qkv,  g_qkv);
    float* attn; cudaGetSymbolAddress((void**)&attn, g_attn);

    // Opt in to >48KB dynamic smem for the attention kernel (idempotent,
    // not a stream op -> graph-capture safe).
    cudaFuncSetAttribute(flash_attn, cudaFuncAttributeMaxDynamicSharedMemorySize,
                         FLASH_SMEM_BYTES);

    // 1) QKV projection: [2048,6144]
    gemm_nt_bias<<<dim3(D3 / 128, SEQ / 128), 256>>>(hidden, w_qkv, b_qkv, qkv, D3, D_EMBED);

    // 2) Causal multi-head attention -> g_attn [2048,2048]
    flash_attn<<<dim3(SEQ / 64, NH), 256, FLASH_SMEM_BYTES>>>(qkv, attn);

    // 3) Output projection
    gemm_nt_bias<<<dim3(D_EMBED / 128, SEQ / 128), 256>>>(attn, w_out, b_out, out, D_EMBED, D_EMBED);
}

// round 5
// speedup vs baseline: 2.0804x; 2.0804x over previous
#include <cuda_runtime.h>
#include <math.h>

#define D_EMBED 2048
#define SEQ     2048
#define NH      32
#define HD      64
#define D3      (3 * D_EMBED)       // 6144
#define QK_SCALE 0.125f             // 64^-0.5

// Scratch (allocation-free rule)
__device__ float g_qkv[SEQ * D3];             // [2048,6144] qkv
__device__ float g_attn[SEQ * D_EMBED];       // [2048,2048] attn out (tf32-rounded)
__device__ float g_hid_t[SEQ * D_EMBED];      // tf32-rounded hidden
__device__ float g_wqkv_t[D3 * D_EMBED];      // tf32-rounded w_qkv
__device__ float g_wout_t[D_EMBED * D_EMBED]; // tf32-rounded w_out

// ===========================================================================
// Helpers (base sm_100 portable: mma.sync / ldmatrix / cp.async only)
// ===========================================================================
__device__ __forceinline__ unsigned smem_u32(const void* p) {
    unsigned a;
    asm("{ .reg .u64 t; cvta.to.shared.u64 t, %1; cvt.u32.u64 %0, t; }"
        : "=r"(a) : "l"(p));
    return a;
}
#define CP_ASYNC16(dst, src) \
    asm volatile("cp.async.cg.shared.global [%0], [%1], 16;" :: "r"(dst), "l"(src))
#define CP_COMMIT() asm volatile("cp.async.commit_group;" ::: "memory")
#define CP_WAIT(n)  asm volatile("cp.async.wait_group %0;" :: "n"(n) : "memory")

__device__ __forceinline__ void ldsm_x4(unsigned r[4], unsigned addr) {
    asm volatile("ldmatrix.sync.aligned.m8n8.x4.shared.b16 {%0,%1,%2,%3}, [%4];"
                 : "=r"(r[0]), "=r"(r[1]), "=r"(r[2]), "=r"(r[3]) : "r"(addr));
}
__device__ __forceinline__ void mma_tf32(float c[4], const unsigned a[4],
                                         unsigned b0, unsigned b1) {
    asm volatile("mma.sync.aligned.m16n8k8.row.col.f32.tf32.tf32.f32 "
                 "{%0,%1,%2,%3}, {%4,%5,%6,%7}, {%8,%9}, {%0,%1,%2,%3};"
                 : "+f"(c[0]), "+f"(c[1]), "+f"(c[2]), "+f"(c[3])
                 : "r"(a[0]), "r"(a[1]), "r"(a[2]), "r"(a[3]), "r"(b0), "r"(b1));
}
__device__ __forceinline__ float round_tf32(float x) {
    unsigned u;
    asm("cvt.rna.tf32.f32 %0, %1;" : "=r"(u) : "f"(x));
    return __uint_as_float(u);
}

// ===========================================================================
// Elementwise RN-round-to-tf32 (mma.sync tf32 truncates otherwise -> bias)
// ===========================================================================
__global__ void round_tf32_kernel(const float4* __restrict__ src,
                                  float4* __restrict__ dst, int n4)
{
    int i = blockIdx.x * blockDim.x + threadIdx.x;
    if (i < n4) {
        float4 v = src[i];
        v.x = round_tf32(v.x); v.y = round_tf32(v.y);
        v.z = round_tf32(v.z); v.w = round_tf32(v.w);
        dst[i] = v;
    }
}

// ===========================================================================
// tf32 mma.sync NT GEMM + bias: C[M,N] = A[M,K]*B[N,K]^T + bias[N]
// BM=BN=128, BK=32, 3-stage cp.async, 8 warps (2 m x 4 n), warp tile 64x32.
// XOR-16B swizzle on 128B rows; fragments via ldmatrix.x4.b16-as-tf32.
// ===========================================================================
#define BM 128
#define BN 128
#define BK 32
#define STAGES 3
#define AS_BYTES (BM * 128)                 // 16 KB
#define BS_BYTES (BN * 128)                 // 16 KB
#define STG_BYTES (AS_BYTES + BS_BYTES)     // 32 KB
#define GEMM_SMEM_BYTES (STAGES * STG_BYTES)  // 96 KB

__global__ __launch_bounds__(256, 2)
void gemm_tf32mma(const float* __restrict__ A, const float* __restrict__ B,
                  const float* __restrict__ bias, float* __restrict__ C,
                  int N, int K)
{
    extern __shared__ char smem[];
    const unsigned sb = smem_u32(smem);
    const int tid  = threadIdx.x;
    const int wid  = tid >> 5;
    const int lane = tid & 31;
    const int m0 = blockIdx.y * BM;
    const int n0 = blockIdx.x * BN;
    const int m_off = (wid & 1) * 64;       // warp m offset within CTA tile
    const int n_off = (wid >> 1) * 32;      // warp n offset
    const int NC = K / BK;

    float acc[4][4][4];                     // [m-frag][n-frag][c0..c3]
#pragma unroll
    for (int mi = 0; mi < 4; mi++)
#pragma unroll
        for (int nf = 0; nf < 4; nf++)
#pragma unroll
            for (int j = 0; j < 4; j++) acc[mi][nf][j] = 0.f;

    // --- producer: one BK=32 chunk (A 128x32 + B 128x32) into stage st
    auto load_chunk = [&](int ck, int st) {
        const unsigned ab = sb + st * STG_BYTES;
        const unsigned bb = ab + AS_BYTES;
        const float* Ag = A + (size_t)m0 * K + ck * BK;
        const float* Bg = B + (size_t)n0 * K + ck * BK;
#pragma unroll
        for (int i = 0; i < 4; i++) {
            int seg = tid + i * 256;        // 0..1023
            int r = seg >> 3, s16 = seg & 7;
            unsigned col = (unsigned)(s16 * 16) ^ ((unsigned)(r & 7) * 16);
            CP_ASYNC16(ab + r * 128 + col, Ag + (size_t)r * K + s16 * 4);
            CP_ASYNC16(bb + r * 128 + col, Bg + (size_t)r * K + s16 * 4);
        }
        CP_COMMIT();
    };

    // --- per-lane ldmatrix addressing
    const int rA  = lane & 15;                    // A: row within 16-row m-frag
    const unsigned hiA = ((lane >> 4) & 1) * 16;  // A: k cols 0-3 / 4-7
    const int rB  = (lane & 7) + ((lane >> 4) & 1) * 8;  // B: n row within 16
    const unsigned hiB = ((lane >> 3) & 1) * 16;         // B: k half

    for (int p = 0; p < STAGES - 1; p++) load_chunk(p, p);

    for (int c = 0; c < NC; c++) {
        CP_WAIT(STAGES - 2);            // chunk c resident
        __syncthreads();                // all warps done with stage we reload
        if (c + STAGES - 1 < NC) load_chunk(c + STAGES - 1, (c + STAGES - 1) % STAGES);
        else                     CP_COMMIT();   // keep group FIFO aligned

        const unsigned ab = sb + (c % STAGES) * STG_BYTES;
        const unsigned bb = ab + AS_BYTES;
#pragma unroll
        for (int ks = 0; ks < 4; ks++) {        // 4 k-steps of 8
            unsigned a[4][4], b[2][4];
#pragma unroll
            for (int mi = 0; mi < 4; mi++) {
                int row = m_off + mi * 16 + rA;
                unsigned col = ((unsigned)(ks * 32) + hiA) ^ ((unsigned)(row & 7) * 16);
                ldsm_x4(a[mi], ab + row * 128 + col);
            }
#pragma unroll
            for (int nj = 0; nj < 2; nj++) {
                int row = n_off + nj * 16 + rB;
                unsigned col = ((unsigned)(ks * 32) + hiB) ^ ((unsigned)(row & 7) * 16);
                ldsm_x4(b[nj], bb + row * 128 + col);
            }
#pragma unroll
            for (int mi = 0; mi < 4; mi++)
#pragma unroll
                for (int nf = 0; nf < 4; nf++)
                    mma_tf32(acc[mi][nf], a[mi],
                             b[nf >> 1][(nf & 1) * 2], b[nf >> 1][(nf & 1) * 2 + 1]);
        }
    }

    // --- epilogue: bias + store (thread owns rows g,g+8; cols 2c,2c+1 per frag)
    const int g = lane >> 2;
    const int cc = (lane & 3) * 2;
#pragma unroll
    for (int nf = 0; nf < 4; nf++) {
        int col = n0 + n_off + nf * 8 + cc;
        float b0 = bias[col], b1 = bias[col + 1];
#pragma unroll
        for (int mi = 0; mi < 4; mi++) {
            int r = m0 + m_off + mi * 16 + g;
            float2 v0 = make_float2(acc[mi][nf][0] + b0, acc[mi][nf][1] + b1);
            float2 v1 = make_float2(acc[mi][nf][2] + b0, acc[mi][nf][3] + b1);
            *(float2*)(C + (size_t)r * N + col)       = v0;
            *(float2*)(C + (size_t)(r + 8) * N + col) = v1;
        }
    }
}

// ===========================================================================
// Causal flash attention, fp32 SIMT (R2-proven), tf32-rounded output.
// ===========================================================================
#define SM_QST   0
#define SM_KST   (SM_QST + 64 * 64)
#define SM_VS    (SM_KST + 64 * 64)
#define SM_SS    (SM_VS  + 64 * 64)
#define SM_MROW  (SM_SS  + 64 * 65)
#define SM_LROW  (SM_MROW + 64)
#define SM_AROW  (SM_LROW + 64)
#define SM_TOTAL (SM_AROW + 64)
#define FLASH_SMEM_BYTES (SM_TOTAL * 4)

__global__ __launch_bounds__(256)
void flash_attn(const float* __restrict__ qkv, float* __restrict__ attn)
{
    extern __shared__ float sm[];
    float (*QsT)[64] = (float (*)[64])(sm + SM_QST);
    float (*KsT)[64] = (float (*)[64])(sm + SM_KST);
    float (*Vs)[64]  = (float (*)[64])(sm + SM_VS);
    float (*Ss)[65]  = (float (*)[65])(sm + SM_SS);
    float* mrow = sm + SM_MROW;
    float* lrow = sm + SM_LROW;
    float* arow = sm + SM_AROW;

    const int tid = threadIdx.x;
    const int ty = tid >> 4;
    const int tx = tid & 15;
    const int r0 = ty * 4;
    const int c0 = tx * 4;
    const int qb = blockIdx.x;
    const int h  = blockIdx.y;
    const int qbase = qb * 64;

#pragma unroll
    for (int j = 0; j < 4; j++) {
        int c  = tid + j * 256;
        int r  = c >> 4;
        int d4 = (c & 15) << 2;
        float4 v = *(const float4*)(qkv + (size_t)(qbase + r) * D3 + h * HD + d4);
        QsT[d4 + 0][r] = v.x * QK_SCALE; QsT[d4 + 1][r] = v.y * QK_SCALE;
        QsT[d4 + 2][r] = v.z * QK_SCALE; QsT[d4 + 3][r] = v.w * QK_SCALE;
    }
    if (tid < 64) { mrow[tid] = -1e30f; lrow[tid] = 0.f; }

    float o[4][4];
#pragma unroll
    for (int i = 0; i < 4; i++)
#pragma unroll
        for (int j = 0; j < 4; j++) o[i][j] = 0.f;

    for (int kt = 0; kt <= qb; kt++) {
        __syncthreads();
#pragma unroll
        for (int j = 0; j < 4; j++) {
            int c  = tid + j * 256;
            int r  = c >> 4;
            int d4 = (c & 15) << 2;
            size_t base = (size_t)(kt * 64 + r) * D3 + h * HD + d4;
            float4 kv = *(const float4*)(qkv + D_EMBED + base);
            KsT[d4 + 0][r] = kv.x; KsT[d4 + 1][r] = kv.y;
            KsT[d4 + 2][r] = kv.z; KsT[d4 + 3][r] = kv.w;
            float4 vv = *(const float4*)(qkv + 2 * D_EMBED + base);
            *(float4*)&Vs[r][d4] = vv;
        }
        __syncthreads();

        float s[4][4];
#pragma unroll
        for (int i = 0; i < 4; i++)
#pragma unroll
            for (int j = 0; j < 4; j++) s[i][j] = 0.f;
#pragma unroll 16
        for (int d = 0; d < 64; d++) {
            float4 qa = *(const float4*)&QsT[d][r0];
            float4 kb = *(const float4*)&KsT[d][c0];
            float qv[4] = {qa.x, qa.y, qa.z, qa.w};
            float kv[4] = {kb.x, kb.y, kb.z, kb.w};
#pragma unroll
            for (int i = 0; i < 4; i++)
#pragma unroll
                for (int j = 0; j < 4; j++)
                    s[i][j] = fmaf(qv[i], kv[j], s[i][j]);
        }

        const bool diag = (kt == qb);
#pragma unroll
        for (int i = 0; i < 4; i++)
#pragma unroll
            for (int j = 0; j < 4; j++) {
                if (diag && (c0 + j) > (r0 + i)) s[i][j] = -1e30f;
                Ss[r0 + i][c0 + j] = s[i][j];
            }
        __syncthreads();

        if (tid < 64) {
            float m_old = mrow[tid];
            float mx = m_old;
            const float* srow = &Ss[tid][0];
#pragma unroll 16
            for (int c = 0; c < 64; c++) mx = fmaxf(mx, srow[c]);
            mrow[tid] = mx;
            arow[tid] = __expf(m_old - mx);
        }
        __syncthreads();

#pragma unroll
        for (int i = 0; i < 4; i++) {
            float mi = mrow[r0 + i];
            float ai = arow[r0 + i];
#pragma unroll
            for (int j = 0; j < 4; j++) {
                float p = __expf(s[i][j] - mi);
                Ss[r0 + i][c0 + j] = p;
                o[i][j] *= ai;
            }
        }
        __syncthreads();

        if (tid < 64) {
            float sum = 0.f;
            const float* srow = &Ss[tid][0];
#pragma unroll 16
            for (int c = 0; c < 64; c++) sum += srow[c];
            lrow[tid] = lrow[tid] * arow[tid] + sum;
        }

#pragma unroll 8
        for (int k = 0; k < 64; k++) {
            float4 vv = *(const float4*)&Vs[k][c0];
            float p0 = Ss[r0 + 0][k], p1 = Ss[r0 + 1][k];
            float p2 = Ss[r0 + 2][k], p3 = Ss[r0 + 3][k];
            o[0][0] = fmaf(p0, vv.x, o[0][0]); o[0][1] = fmaf(p0, vv.y, o[0][1]);
            o[0][2] = fmaf(p0, vv.z, o[0][2]); o[0][3] = fmaf(p0, vv.w, o[0][3]);
            o[1][0] = fmaf(p1, vv.x, o[1][0]); o[1][1] = fmaf(p1, vv.y, o[1][1]);
            o[1][2] = fmaf(p1, vv.z, o[1][2]); o[1][3] = fmaf(p1, vv.w, o[1][3]);
            o[2][0] = fmaf(p2, vv.x, o[2][0]); o[2][1] = fmaf(p2, vv.y, o[2][1]);
            o[2][2] = fmaf(p2, vv.z, o[2][2]); o[2][3] = fmaf(p2, vv.w, o[2][3]);
            o[3][0] = fmaf(p3, vv.x, o[3][0]); o[3][1] = fmaf(p3, vv.y, o[3][1]);
            o[3][2] = fmaf(p3, vv.z, o[3][2]); o[3][3] = fmaf(p3, vv.w, o[3][3]);
        }
    }
    __syncthreads();

#pragma unroll
    for (int i = 0; i < 4; i++) {
        float linv = 1.f / lrow[r0 + i];
        float4 ov = make_float4(round_tf32(o[i][0] * linv), round_tf32(o[i][1] * linv),
                                round_tf32(o[i][2] * linv), round_tf32(o[i][3] * linv));
        *(float4*)(attn + (size_t)(qbase + r0 + i) * D_EMBED + h * HD + c0) = ov;
    }
}

// ===========================================================================
extern "C" void kernel_launch(void* const* d_in, const int* in_sizes, int n_in,
                              void* d_out, int out_size)
{
    const float* hidden = (const float*)d_in[0];
    const float* w_qkv  = (const float*)d_in[1];
    const float* b_qkv  = (const float*)d_in[2];
    const float* w_out  = (const float*)d_in[3];
    const float* b_out  = (const float*)d_in[4];
    float* out = (float*)d_out;

    float *qkv, *attn, *hid_t, *wqkv_t, *wout_t;
    cudaGetSymbolAddress((void**)&qkv,    g_qkv);
    cudaGetSymbolAddress((void**)&attn,   g_attn);
    cudaGetSymbolAddress((void**)&hid_t,  g_hid_t);
    cudaGetSymbolAddress((void**)&wqkv_t, g_wqkv_t);
    cudaGetSymbolAddress((void**)&wout_t, g_wout_t);

    cudaFuncSetAttribute(gemm_tf32mma, cudaFuncAttributeMaxDynamicSharedMemorySize,
                         GEMM_SMEM_BYTES);
    cudaFuncSetAttribute(flash_attn, cudaFuncAttributeMaxDynamicSharedMemorySize,
                         FLASH_SMEM_BYTES);

    // RN-round GEMM inputs to tf32
    {
        int n4h = SEQ * D_EMBED / 4;
        round_tf32_kernel<<<(n4h + 255) / 256, 256>>>((const float4*)hidden, (float4*)hid_t, n4h);
        int n4w = D3 * D_EMBED / 4;
        round_tf32_kernel<<<(n4w + 255) / 256, 256>>>((const float4*)w_qkv, (float4*)wqkv_t, n4w);
        int n4o = D_EMBED * D_EMBED / 4;
        round_tf32_kernel<<<(n4o + 255) / 256, 256>>>((const float4*)w_out, (float4*)wout_t, n4o);
    }

    // 1) QKV projection (tf32 mma.sync)
    gemm_tf32mma<<<dim3(D3 / BN, SEQ / BM), 256, GEMM_SMEM_BYTES>>>(
        hid_t, wqkv_t, b_qkv, qkv, D3, D_EMBED);

    // 2) Causal multi-head attention (fp32 SIMT)
    flash_attn<<<dim3(SEQ / 64, NH), 256, FLASH_SMEM_BYTES>>>(qkv, attn);

    // 3) Output projection (tf32 mma.sync)
    gemm_tf32mma<<<dim3(D_EMBED / BN, SEQ / BM), 256, GEMM_SMEM_BYTES>>>(
        attn, wout_t, b_out, out, D_EMBED, D_EMBED);
}

// round 7
// speedup vs baseline: 3.5456x; 1.7043x over previous
#include <cuda_runtime.h>
#include <math.h>

#define D_EMBED 2048
#define SEQ     2048
#define NH      32
#define HD      64
#define D3      (3 * D_EMBED)       // 6144

// Scratch (allocation-free rule)
__device__ float g_qkv[SEQ * D3];             // [2048,6144] qkv (tf32-rounded)
__device__ float g_attn[SEQ * D_EMBED];       // [2048,2048] attn out (tf32-rounded)
__device__ float g_hid_t[SEQ * D_EMBED];      // tf32-rounded hidden
__device__ float g_wqkv_t[D3 * D_EMBED];      // tf32-rounded w_qkv
__device__ float g_wout_t[D_EMBED * D_EMBED]; // tf32-rounded w_out

// ===========================================================================
// Helpers (base sm_100 portable: mma.sync / ldmatrix / cp.async only)
// ===========================================================================
__device__ __forceinline__ unsigned smem_u32(const void* p) {
    unsigned a;
    asm("{ .reg .u64 t; cvta.to.shared.u64 t, %1; cvt.u32.u64 %0, t; }"
        : "=r"(a) : "l"(p));
    return a;
}
#define CP_ASYNC16(dst, src) \
    asm volatile("cp.async.cg.shared.global [%0], [%1], 16;" :: "r"(dst), "l"(src))
#define CP_COMMIT() asm volatile("cp.async.commit_group;" ::: "memory")
#define CP_WAIT(n)  asm volatile("cp.async.wait_group %0;" :: "n"(n) : "memory")

__device__ __forceinline__ void ldsm_x4(unsigned r[4], unsigned addr) {
    asm volatile("ldmatrix.sync.aligned.m8n8.x4.shared.b16 {%0,%1,%2,%3}, [%4];"
                 : "=r"(r[0]), "=r"(r[1]), "=r"(r[2]), "=r"(r[3]) : "r"(addr));
}
__device__ __forceinline__ void mma_tf32(float c[4], const unsigned a[4],
                                         unsigned b0, unsigned b1) {
    asm volatile("mma.sync.aligned.m16n8k8.row.col.f32.tf32.tf32.f32 "
                 "{%0,%1,%2,%3}, {%4,%5,%6,%7}, {%8,%9}, {%0,%1,%2,%3};"
                 : "+f"(c[0]), "+f"(c[1]), "+f"(c[2]), "+f"(c[3])
                 : "r"(a[0]), "r"(a[1]), "r"(a[2]), "r"(a[3]), "r"(b0), "r"(b1));
}
__device__ __forceinline__ float round_tf32(float x) {
    unsigned u;
    asm("cvt.rna.tf32.f32 %0, %1;" : "=r"(u) : "f"(x));
    return __uint_as_float(u);
}
__device__ __forceinline__ float fast_exp2(float x) {
    float y;
    asm("ex2.approx.f32 %0, %1;" : "=f"(y) : "f"(x));
    return y;
}

// ===========================================================================
// Elementwise RN-round-to-tf32
// ===========================================================================
__global__ void round_tf32_kernel(const float4* __restrict__ src,
                                  float4* __restrict__ dst, int n4)
{
    int i = blockIdx.x * blockDim.x + threadIdx.x;
    if (i < n4) {
        float4 v = src[i];
        v.x = round_tf32(v.x); v.y = round_tf32(v.y);
        v.z = round_tf32(v.z); v.w = round_tf32(v.w);
        dst[i] = v;
    }
}

// ===========================================================================
// tf32 mma.sync NT GEMM + bias (exact R5-proven mainloop).
// round_c: RNA-round output to tf32.
// ===========================================================================
#define BM 128
#define BN 128
#define BK 32
#define STAGES 3
#define AS_BYTES (BM * 128)
#define BS_BYTES (BN * 128)
#define STG_BYTES (AS_BYTES + BS_BYTES)
#define GEMM_SMEM_BYTES (STAGES * STG_BYTES)  // 96 KB

__global__ __launch_bounds__(256, 2)
void gemm_tf32mma(const float* __restrict__ A, const float* __restrict__ B,
                  const float* __restrict__ bias, float* __restrict__ C,
                  int N, int K, int round_c)
{
    extern __shared__ char smem[];
    const unsigned sb = smem_u32(smem);
    const int tid  = threadIdx.x;
    const int wid  = tid >> 5;
    const int lane = tid & 31;
    const int m0 = blockIdx.y * BM;
    const int n0 = blockIdx.x * BN;
    const int m_off = (wid & 1) * 64;
    const int n_off = (wid >> 1) * 32;
    const int NC = K / BK;

    float acc[4][4][4];
#pragma unroll
    for (int mi = 0; mi < 4; mi++)
#pragma unroll
        for (int nf = 0; nf < 4; nf++)
#pragma unroll
            for (int j = 0; j < 4; j++) acc[mi][nf][j] = 0.f;

    auto load_chunk = [&](int ck, int st) {
        const unsigned ab = sb + st * STG_BYTES;
        const unsigned bb = ab + AS_BYTES;
        const float* Ag = A + (size_t)m0 * K + ck * BK;
        const float* Bg = B + (size_t)n0 * K + ck * BK;
#pragma unroll
        for (int i = 0; i < 4; i++) {
            int seg = tid + i * 256;
            int r = seg >> 3, s16 = seg & 7;
            unsigned col = (unsigned)(s16 * 16) ^ ((unsigned)(r & 7) * 16);
            CP_ASYNC16(ab + r * 128 + col, Ag + (size_t)r * K + s16 * 4);
            CP_ASYNC16(bb + r * 128 + col, Bg + (size_t)r * K + s16 * 4);
        }
        CP_COMMIT();
    };

    const int rA  = lane & 15;
    const unsigned hiA = ((lane >> 4) & 1) * 16;
    const int rB  = (lane & 7) + ((lane >> 4) & 1) * 8;
    const unsigned hiB = ((lane >> 3) & 1) * 16;

    for (int p = 0; p < STAGES - 1; p++) load_chunk(p, p);

    for (int c = 0; c < NC; c++) {
        CP_WAIT(STAGES - 2);
        __syncthreads();
        if (c + STAGES - 1 < NC) load_chunk(c + STAGES - 1, (c + STAGES - 1) % STAGES);
        else                     CP_COMMIT();

        const unsigned ab = sb + (c % STAGES) * STG_BYTES;
        const unsigned bb = ab + AS_BYTES;
#pragma unroll
        for (int ks = 0; ks < 4; ks++) {
            unsigned a[4][4], b[2][4];
#pragma unroll
            for (int mi = 0; mi < 4; mi++) {
                int row = m_off + mi * 16 + rA;
                unsigned col = ((unsigned)(ks * 32) + hiA) ^ ((unsigned)(row & 7) * 16);
                ldsm_x4(a[mi], ab + row * 128 + col);
            }
#pragma unroll
            for (int nj = 0; nj < 2; nj++) {
                int row = n_off + nj * 16 + rB;
                unsigned col = ((unsigned)(ks * 32) + hiB) ^ ((unsigned)(row & 7) * 16);
                ldsm_x4(b[nj], bb + row * 128 + col);
            }
#pragma unroll
            for (int mi = 0; mi < 4; mi++)
#pragma unroll
                for (int nf = 0; nf < 4; nf++)
                    mma_tf32(acc[mi][nf], a[mi],
                             b[nf >> 1][(nf & 1) * 2], b[nf >> 1][(nf & 1) * 2 + 1]);
        }
    }

    const int g = lane >> 2;
    const int cc = (lane & 3) * 2;
#pragma unroll
    for (int nf = 0; nf < 4; nf++) {
        int col = n0 + n_off + nf * 8 + cc;
        float b0 = bias[col], b1 = bias[col + 1];
#pragma unroll
        for (int mi = 0; mi < 4; mi++) {
            int r = m0 + m_off + mi * 16 + g;
            float2 v0 = make_float2(acc[mi][nf][0] + b0, acc[mi][nf][1] + b1);
            float2 v1 = make_float2(acc[mi][nf][2] + b0, acc[mi][nf][3] + b1);
            if (round_c) {
                v0.x = round_tf32(v0.x); v0.y = round_tf32(v0.y);
                v1.x = round_tf32(v1.x); v1.y = round_tf32(v1.y);
            }
            *(float2*)(C + (size_t)r * N + col)       = v0;
            *(float2*)(C + (size_t)(r + 8) * N + col) = v1;
        }
    }
}

// ===========================================================================
// tf32 mma.sync causal flash attention.
// CTA = (q-tile of 64, head); 4 warps x 16 q-rows. K cp.async double-buffered;
// V transposed on load (stride-68-float rows, conflict-free STS + ldmatrix);
// P round-trips through per-warp swizzled smem to become A-fragments.
// Softmax in log2 domain (QK_SCALE*log2e folded), quad shfl reductions.
// ===========================================================================
#define FA_Q 0
#define FA_K 16384                  // 2 stages x 16 KB
#define FA_V 49152                  // 64 x 272 B = 17408
#define FA_P 66560                  // 4 warps x 4 KB
#define FA_SMEM 82944
#define CST 0.1803368801111137f     // (1/8) * log2(e)

__global__ __launch_bounds__(128)
void flash_attn_mma(const float* __restrict__ qkv, float* __restrict__ attn)
{
    extern __shared__ char smc[];
    const unsigned sb = smem_u32(smc);
    const int tid = threadIdx.x;
    const int wid = tid >> 5, lane = tid & 31;
    const int qb = blockIdx.x, h = blockIdx.y;
    const int qbase = qb * 64;
    const int g = lane >> 2, qq = lane & 3;

    const int rA = lane & 15;
    const unsigned hiA = ((lane >> 4) & 1) * 16;
    const int rB = (lane & 7) + ((lane >> 4) & 1) * 8;
    const unsigned hiB = ((lane >> 3) & 1) * 16;

    // 64x64 f32 tile copy: 256B rows, XOR-16B swizzle per 128B half
    auto tile_async = [&](const float* gsrc, unsigned dstb) {
#pragma unroll
        for (int i = 0; i < 8; i++) {
            int u = tid + i * 128;
            int r = u >> 4, hs = (u >> 3) & 1, s16 = u & 7;
            unsigned off = ((unsigned)(s16 * 16)) ^ ((unsigned)(r & 7) * 16);
            CP_ASYNC16(dstb + (unsigned)(r * 256 + hs * 128) + off,
                       gsrc + (size_t)r * D3 + hs * 32 + s16 * 4);
        }
    };

    const float* Qg = qkv + (size_t)qbase * D3 + h * HD;
    const float* Kg = qkv + D_EMBED + h * HD;
    const float* Vg = qkv + 2 * D_EMBED + h * HD;

    tile_async(Qg, sb + FA_Q);
    tile_async(Kg, sb + FA_K);      // K tile 0 -> stage 0
    CP_COMMIT();

    float o[8][4];
#pragma unroll
    for (int nf = 0; nf < 8; nf++)
#pragma unroll
        for (int j = 0; j < 4; j++) o[nf][j] = 0.f;
    float m0 = -1e30f, m1 = -1e30f, l0 = 0.f, l1 = 0.f;

    for (int kt = 0; kt <= qb; kt++) {
        const int st = kt & 1;
        CP_WAIT(0);                 // K[kt] (and Q on first iter) resident
        __syncthreads();            // all warps done with prev tile (VsT reuse safe)

        // ---- S = Q K^T  (16 q-rows x 64 keys per warp)
        const unsigned kb = sb + FA_K + st * 16384;
        float sf[8][4];
#pragma unroll
        for (int nf = 0; nf < 8; nf++)
#pragma unroll
            for (int j = 0; j < 4; j++) sf[nf][j] = 0.f;
#pragma unroll
        for (int ks = 0; ks < 8; ks++) {
            unsigned a[4];
            {
                int row = wid * 16 + rA;
                unsigned addr = sb + FA_Q + (unsigned)(row * 256 + (ks >> 2) * 128)
                              + (((unsigned)((ks & 3) * 32) + hiA) ^ ((unsigned)(row & 7) * 16));
                ldsm_x4(a, addr);
            }
            unsigned b[4][4];
#pragma unroll
            for (int nj = 0; nj < 4; nj++) {
                int row = nj * 16 + rB;
                unsigned addr = kb + (unsigned)(row * 256 + (ks >> 2) * 128)
                              + (((unsigned)((ks & 3) * 32) + hiB) ^ ((unsigned)(row & 7) * 16));
                ldsm_x4(b[nj], addr);
            }
#pragma unroll
            for (int nf = 0; nf < 8; nf++)
                mma_tf32(sf[nf], a, b[nf >> 1][(nf & 1) * 2], b[nf >> 1][(nf & 1) * 2 + 1]);
        }

        // ---- prefetch next K tile into the other stage
        if (kt < qb)
            tile_async(Kg + (size_t)(kt + 1) * 64 * D3, sb + FA_K + (st ^ 1) * 16384);
        CP_COMMIT();

        // ---- V gather-transpose: VsT[d][key], row stride 272B
        {
            int d = tid & 63, kh = tid >> 6;
            const float* src = Vg + (size_t)kt * 64 * D3 + d;
#pragma unroll
            for (int j = 0; j < 8; j++) {
                int k0 = kh * 32 + j * 4;
                float4 v;
                v.x = src[(size_t)(k0 + 0) * D3];
                v.y = src[(size_t)(k0 + 1) * D3];
                v.z = src[(size_t)(k0 + 2) * D3];
                v.w = src[(size_t)(k0 + 3) * D3];
                *(float4*)(smc + FA_V + d * 272 + k0 * 4) = v;
            }
        }

        // ---- online softmax on fragments (log2 domain)
        if (kt == qb) {
            int r0 = qbase + wid * 16 + g;
#pragma unroll
            for (int nf = 0; nf < 8; nf++) {
                int col = qbase + nf * 8 + qq * 2;
                if (col > r0)         sf[nf][0] = -1e30f;
                if (col + 1 > r0)     sf[nf][1] = -1e30f;
                if (col > r0 + 8)     sf[nf][2] = -1e30f;
                if (col + 1 > r0 + 8) sf[nf][3] = -1e30f;
            }
        }
        float t0 = -1e30f, t1 = -1e30f;
#pragma unroll
        for (int nf = 0; nf < 8; nf++) {
            t0 = fmaxf(t0, fmaxf(sf[nf][0], sf[nf][1]));
            t1 = fmaxf(t1, fmaxf(sf[nf][2], sf[nf][3]));
        }
        t0 = fmaxf(t0, __shfl_xor_sync(0xffffffffu, t0, 1));
        t0 = fmaxf(t0, __shfl_xor_sync(0xffffffffu, t0, 2));
        t1 = fmaxf(t1, __shfl_xor_sync(0xffffffffu, t1, 1));
        t1 = fmaxf(t1, __shfl_xor_sync(0xffffffffu, t1, 2));
        const float mn0 = fmaxf(m0, t0 * CST);
        const float mn1 = fmaxf(m1, t1 * CST);
        const float al0 = fast_exp2(m0 - mn0);
        const float al1 = fast_exp2(m1 - mn1);
        m0 = mn0; m1 = mn1;

        float ps0 = 0.f, ps1 = 0.f;
        const int pwo = FA_P + wid * 4096;
#pragma unroll
        for (int nf = 0; nf < 8; nf++) {
            float p00 = round_tf32(fast_exp2(fmaf(sf[nf][0], CST, -mn0)));
            float p01 = round_tf32(fast_exp2(fmaf(sf[nf][1], CST, -mn0)));
            float p10 = round_tf32(fast_exp2(fmaf(sf[nf][2], CST, -mn1)));
            float p11 = round_tf32(fast_exp2(fmaf(sf[nf][3], CST, -mn1)));
            ps0 += p00 + p01; ps1 += p10 + p11;
            unsigned offh = ((unsigned)((nf & 3) * 32 + qq * 8)) ^ ((unsigned)g * 16);
            int base = pwo + (nf >> 2) * 128 + (int)offh;
            *(float2*)(smc + base + g * 256)       = make_float2(p00, p01);
            *(float2*)(smc + base + (g + 8) * 256) = make_float2(p10, p11);
        }
        ps0 += __shfl_xor_sync(0xffffffffu, ps0, 1);
        ps0 += __shfl_xor_sync(0xffffffffu, ps0, 2);
        ps1 += __shfl_xor_sync(0xffffffffu, ps1, 1);
        ps1 += __shfl_xor_sync(0xffffffffu, ps1, 2);
        l0 = l0 * al0 + ps0;
        l1 = l1 * al1 + ps1;
#pragma unroll
        for (int nf = 0; nf < 8; nf++) {
            o[nf][0] *= al0; o[nf][1] *= al0;
            o[nf][2] *= al1; o[nf][3] *= al1;
        }
        __syncwarp();               // P visible within warp
        __syncthreads();            // VsT visible to all warps

        // ---- O += P * V  (P A-frags from smem, V^T B-frags)
#pragma unroll
        for (int ks = 0; ks < 8; ks++) {
            unsigned a[4];
            {
                int row = rA;
                unsigned addr = sb + (unsigned)(pwo + row * 256 + (ks >> 2) * 128)
                              + (((unsigned)((ks & 3) * 32) + hiA) ^ ((unsigned)(row & 7) * 16));
                ldsm_x4(a, addr);
            }
            unsigned b[4][4];
#pragma unroll
            for (int nj = 0; nj < 4; nj++) {
                int row = nj * 16 + rB;
                unsigned addr = sb + (unsigned)(FA_V + row * 272 + ks * 32) + hiB;
                ldsm_x4(b[nj], addr);
            }
#pragma unroll
            for (int nf = 0; nf < 8; nf++)
                mma_tf32(o[nf], a, b[nf >> 1][(nf & 1) * 2], b[nf >> 1][(nf & 1) * 2 + 1]);
        }
    }

    // ---- epilogue: normalize, tf32-round, store
    const float i0 = 1.f / l0, i1 = 1.f / l1;
    const int r0 = qbase + wid * 16 + g;
#pragma unroll
    for (int nf = 0; nf < 8; nf++) {
        int col = h * HD + nf * 8 + qq * 2;
        float2 v0 = make_float2(round_tf32(o[nf][0] * i0), round_tf32(o[nf][1] * i0));
        float2 v1 = make_float2(round_tf32(o[nf][2] * i1), round_tf32(o[nf][3] * i1));
        *(float2*)(attn + (size_t)r0 * D_EMBED + col)       = v0;
        *(float2*)(attn + (size_t)(r0 + 8) * D_EMBED + col) = v1;
    }
}

// ===========================================================================
extern "C" void kernel_launch(void* const* d_in, const int* in_sizes, int n_in,
                              void* d_out, int out_size)
{
    const float* hidden = (const float*)d_in[0];
    const float* w_qkv  = (const float*)d_in[1];
    const float* b_qkv  = (const float*)d_in[2];
    const float* w_out  = (const float*)d_in[3];
    const float* b_out  = (const float*)d_in[4];
    float* out = (float*)d_out;

    float *qkv, *attn, *hid_t, *wqkv_t, *wout_t;
    cudaGetSymbolAddress((void**)&qkv,    g_qkv);
    cudaGetSymbolAddress((void**)&attn,   g_attn);
    cudaGetSymbolAddress((void**)&hid_t,  g_hid_t);
    cudaGetSymbolAddress((void**)&wqkv_t, g_wqkv_t);
    cudaGetSymbolAddress((void**)&wout_t, g_wout_t);

    cudaFuncSetAttribute(gemm_tf32mma, cudaFuncAttributeMaxDynamicSharedMemorySize,
                         GEMM_SMEM_BYTES);
    cudaFuncSetAttribute(flash_attn_mma, cudaFuncAttributeMaxDynamicSharedMemorySize,
                         FA_SMEM);

    // RN-round GEMM inputs to tf32
    {
        int n4h = SEQ * D_EMBED / 4;
        round_tf32_kernel<<<(n4h + 255) / 256, 256>>>((const float4*)hidden, (float4*)hid_t, n4h);
        int n4w = D3 * D_EMBED / 4;
        round_tf32_kernel<<<(n4w + 255) / 256, 256>>>((const float4*)w_qkv, (float4*)wqkv_t, n4w);
        int n4o = D_EMBED * D_EMBED / 4;
        round_tf32_kernel<<<(n4o + 255) / 256, 256>>>((const float4*)w_out, (float4*)wout_t, n4o);
    }

    // 1) QKV projection (tf32 mma.sync), output tf32-rounded for attention MMAs
    gemm_tf32mma<<<dim3(D3 / BN, SEQ / BM), 256, GEMM_SMEM_BYTES>>>(
        hid_t, wqkv_t, b_qkv, qkv, D3, D_EMBED, 1);

    // 2) Causal multi-head attention (tf32 mma.sync flash)
    flash_attn_mma<<<dim3(SEQ / 64, NH), 128, FA_SMEM>>>(qkv, attn);

    // 3) Output projection (tf32 mma.sync), full fp32 output
    gemm_tf32mma<<<dim3(D_EMBED / BN, SEQ / BM), 256, GEMM_SMEM_BYTES>>>(
        attn, wout_t, b_out, out, D_EMBED, D_EMBED, 0);
}

// round 9
// speedup vs baseline: 3.8888x; 1.0968x over previous
#include <cuda_runtime.h>
#include <math.h>

#define D_EMBED 2048
#define SEQ     2048
#define NH      32
#define HD      64
#define D3      (3 * D_EMBED)       // 6144

// Scratch (allocation-free rule)
__device__ float g_qkv[SEQ * D3];             // [2048,6144] qkv (tf32-rounded)
__device__ float g_attn[SEQ * D_EMBED];       // [2048,2048] attn out (tf32-rounded)
__device__ float g_hid_t[SEQ * D_EMBED];      // tf32-rounded hidden
__device__ float g_wqkv_t[D3 * D_EMBED];      // tf32-rounded w_qkv
__device__ float g_wout_t[D_EMBED * D_EMBED]; // tf32-rounded w_out

// ===========================================================================
// Helpers (base sm_100 portable: mma.sync / ldmatrix / cp.async only)
// ===========================================================================
__device__ __forceinline__ unsigned smem_u32(const void* p) {
    unsigned a;
    asm("{ .reg .u64 t; cvta.to.shared.u64 t, %1; cvt.u32.u64 %0, t; }"
        : "=r"(a) : "l"(p));
    return a;
}
#define CP_ASYNC16(dst, src) \
    asm volatile("cp.async.cg.shared.global [%0], [%1], 16;" :: "r"(dst), "l"(src))
#define CP_COMMIT() asm volatile("cp.async.commit_group;" ::: "memory")
#define CP_WAIT(n)  asm volatile("cp.async.wait_group %0;" :: "n"(n) : "memory")

__device__ __forceinline__ void ldsm_x4(unsigned r[4], unsigned addr) {
    asm volatile("ldmatrix.sync.aligned.m8n8.x4.shared.b16 {%0,%1,%2,%3}, [%4];"
                 : "=r"(r[0]), "=r"(r[1]), "=r"(r[2]), "=r"(r[3]) : "r"(addr));
}
__device__ __forceinline__ void mma_tf32(float c[4], const unsigned a[4],
                                         unsigned b0, unsigned b1) {
    asm volatile("mma.sync.aligned.m16n8k8.row.col.f32.tf32.tf32.f32 "
                 "{%0,%1,%2,%3}, {%4,%5,%6,%7}, {%8,%9}, {%0,%1,%2,%3};"
                 : "+f"(c[0]), "+f"(c[1]), "+f"(c[2]), "+f"(c[3])
                 : "r"(a[0]), "r"(a[1]), "r"(a[2]), "r"(a[3]), "r"(b0), "r"(b1));
}
__device__ __forceinline__ float round_tf32(float x) {
    unsigned u;
    asm("cvt.rna.tf32.f32 %0, %1;" : "=r"(u) : "f"(x));
    return __uint_as_float(u);
}
__device__ __forceinline__ float fast_exp2(float x) {
    float y;
    asm("ex2.approx.f32 %0, %1;" : "=f"(y) : "f"(x));
    return y;
}

// ===========================================================================
// Elementwise RN-round-to-tf32
// ===========================================================================
__global__ void round_tf32_kernel(const float4* __restrict__ src,
                                  float4* __restrict__ dst, int n4)
{
    int i = blockIdx.x * blockDim.x + threadIdx.x;
    if (i < n4) {
        float4 v = src[i];
        v.x = round_tf32(v.x); v.y = round_tf32(v.y);
        v.z = round_tf32(v.z); v.w = round_tf32(v.w);
        dst[i] = v;
    }
}

// ===========================================================================
// tf32 mma.sync NT GEMM + bias, PERSISTENT grid (kills wave quantization).
// R5-proven mainloop; round_c: RNA-round output to tf32.
// ===========================================================================
#define BM 128
#define BN 128
#define BK 32
#define STAGES 3
#define AS_BYTES (BM * 128)
#define BS_BYTES (BN * 128)
#define STG_BYTES (AS_BYTES + BS_BYTES)
#define GEMM_SMEM_BYTES (STAGES * STG_BYTES)  // 96 KB
#define GEMM_GRID 296                          // 148 SMs x 2 resident CTAs

__global__ __launch_bounds__(256, 2)
void gemm_tf32mma(const float* __restrict__ A, const float* __restrict__ B,
                  const float* __restrict__ bias, float* __restrict__ C,
                  int N, int K, int M, int round_c)
{
    extern __shared__ char smem[];
    const unsigned sb = smem_u32(smem);
    const int tid  = threadIdx.x;
    const int wid  = tid >> 5;
    const int lane = tid & 31;
    const int m_off = (wid & 1) * 64;
    const int n_off = (wid >> 1) * 32;
    const int NC = K / BK;
    const int ntx = N / BN;
    const int ntiles = ntx * (M / BM);

    const int rA  = lane & 15;
    const unsigned hiA = ((lane >> 4) & 1) * 16;
    const int rB  = (lane & 7) + ((lane >> 4) & 1) * 8;
    const unsigned hiB = ((lane >> 3) & 1) * 16;
    const int g = lane >> 2;
    const int cc = (lane & 3) * 2;

    for (int t = blockIdx.x; t < ntiles; t += gridDim.x) {
        const int m0 = (t / ntx) * BM;
        const int n0 = (t % ntx) * BN;

        __syncthreads();            // all warps done reading smem of prev tile

        float acc[4][4][4];
#pragma unroll
        for (int mi = 0; mi < 4; mi++)
#pragma unroll
            for (int nf = 0; nf < 4; nf++)
#pragma unroll
                for (int j = 0; j < 4; j++) acc[mi][nf][j] = 0.f;

        auto load_chunk = [&](int ck, int st) {
            const unsigned ab = sb + st * STG_BYTES;
            const unsigned bb = ab + AS_BYTES;
            const float* Ag = A + (size_t)m0 * K + ck * BK;
            const float* Bg = B + (size_t)n0 * K + ck * BK;
#pragma unroll
            for (int i = 0; i < 4; i++) {
                int seg = tid + i * 256;
                int r = seg >> 3, s16 = seg & 7;
                unsigned col = (unsigned)(s16 * 16) ^ ((unsigned)(r & 7) * 16);
                CP_ASYNC16(ab + r * 128 + col, Ag + (size_t)r * K + s16 * 4);
                CP_ASYNC16(bb + r * 128 + col, Bg + (size_t)r * K + s16 * 4);
            }
            CP_COMMIT();
        };

        for (int p = 0; p < STAGES - 1; p++) load_chunk(p, p);

        for (int c = 0; c < NC; c++) {
            CP_WAIT(STAGES - 2);
            __syncthreads();
            if (c + STAGES - 1 < NC) load_chunk(c + STAGES - 1, (c + STAGES - 1) % STAGES);
            else                     CP_COMMIT();

            const unsigned ab = sb + (c % STAGES) * STG_BYTES;
            const unsigned bb = ab + AS_BYTES;
#pragma unroll
            for (int ks = 0; ks < 4; ks++) {
                unsigned a[4][4], b[2][4];
#pragma unroll
                for (int mi = 0; mi < 4; mi++) {
                    int row = m_off + mi * 16 + rA;
                    unsigned col = ((unsigned)(ks * 32) + hiA) ^ ((unsigned)(row & 7) * 16);
                    ldsm_x4(a[mi], ab + row * 128 + col);
                }
#pragma unroll
                for (int nj = 0; nj < 2; nj++) {
                    int row = n_off + nj * 16 + rB;
                    unsigned col = ((unsigned)(ks * 32) + hiB) ^ ((unsigned)(row & 7) * 16);
                    ldsm_x4(b[nj], bb + row * 128 + col);
                }
#pragma unroll
                for (int mi = 0; mi < 4; mi++)
#pragma unroll
                    for (int nf = 0; nf < 4; nf++)
                        mma_tf32(acc[mi][nf], a[mi],
                                 b[nf >> 1][(nf & 1) * 2], b[nf >> 1][(nf & 1) * 2 + 1]);
            }
        }

#pragma unroll
        for (int nf = 0; nf < 4; nf++) {
            int col = n0 + n_off + nf * 8 + cc;
            float b0 = bias[col], b1 = bias[col + 1];
#pragma unroll
            for (int mi = 0; mi < 4; mi++) {
                int r = m0 + m_off + mi * 16 + g;
                float2 v0 = make_float2(acc[mi][nf][0] + b0, acc[mi][nf][1] + b1);
                float2 v1 = make_float2(acc[mi][nf][2] + b0, acc[mi][nf][3] + b1);
                if (round_c) {
                    v0.x = round_tf32(v0.x); v0.y = round_tf32(v0.y);
                    v1.x = round_tf32(v1.x); v1.y = round_tf32(v1.y);
                }
                *(float2*)(C + (size_t)r * N + col)       = v0;
                *(float2*)(C + (size_t)(r + 8) * N + col) = v1;
            }
        }
    }
}

// ===========================================================================
// tf32 mma.sync causal flash attention (R7-proven) + two scheduling fixes:
//  - LPT: qb = gridDim.x-1-blockIdx.x so longest CTAs start first
//  - V gather LDGs issued into REGISTERS before the S MMA (latency overlap),
//    STS deferred until after S MMA.
// ===========================================================================
#define FA_Q 0
#define FA_K 16384                  // 2 stages x 16 KB
#define FA_V 49152                  // 64 x 272 B = 17408
#define FA_P 66560                  // 4 warps x 4 KB
#define FA_SMEM 82944
#define CST 0.1803368801111137f     // (1/8) * log2(e)

__global__ __launch_bounds__(128)
void flash_attn_mma(const float* __restrict__ qkv, float* __restrict__ attn)
{
    extern __shared__ char smc[];
    const unsigned sb = smem_u32(smc);
    const int tid = threadIdx.x;
    const int wid = tid >> 5, lane = tid & 31;
    const int qb = gridDim.x - 1 - blockIdx.x;     // LPT: big CTAs first
    const int h  = blockIdx.y;
    const int qbase = qb * 64;
    const int g = lane >> 2, qq = lane & 3;

    const int rA = lane & 15;
    const unsigned hiA = ((lane >> 4) & 1) * 16;
    const int rB = (lane & 7) + ((lane >> 4) & 1) * 8;
    const unsigned hiB = ((lane >> 3) & 1) * 16;

    // 64x64 f32 tile copy: 256B rows, XOR-16B swizzle per 128B half
    auto tile_async = [&](const float* gsrc, unsigned dstb) {
#pragma unroll
        for (int i = 0; i < 8; i++) {
            int u = tid + i * 128;
            int r = u >> 4, hs = (u >> 3) & 1, s16 = u & 7;
            unsigned off = ((unsigned)(s16 * 16)) ^ ((unsigned)(r & 7) * 16);
            CP_ASYNC16(dstb + (unsigned)(r * 256 + hs * 128) + off,
                       gsrc + (size_t)r * D3 + hs * 32 + s16 * 4);
        }
    };

    const float* Qg = qkv + (size_t)qbase * D3 + h * HD;
    const float* Kg = qkv + D_EMBED + h * HD;
    const float* Vg = qkv + 2 * D_EMBED + h * HD;

    tile_async(Qg, sb + FA_Q);
    tile_async(Kg, sb + FA_K);      // K tile 0 -> stage 0
    CP_COMMIT();

    float o[8][4];
#pragma unroll
    for (int nf = 0; nf < 8; nf++)
#pragma unroll
        for (int j = 0; j < 4; j++) o[nf][j] = 0.f;
    float m0 = -1e30f, m1 = -1e30f, l0 = 0.f, l1 = 0.f;

    const int vd = tid & 63, vkh = tid >> 6;       // V gather mapping

    for (int kt = 0; kt <= qb; kt++) {
        const int st = kt & 1;
        CP_WAIT(0);                 // K[kt] (and Q on first iter) resident
        __syncthreads();            // all warps done with prev tile (VsT reuse safe)

        // ---- V gather LDGs -> registers (overlap with S MMA below)
        float4 vr[8];
        {
            const float* src = Vg + (size_t)kt * 64 * D3 + vd;
#pragma unroll
            for (int j = 0; j < 8; j++) {
                int k0 = vkh * 32 + j * 4;
                vr[j].x = src[(size_t)(k0 + 0) * D3];
                vr[j].y = src[(size_t)(k0 + 1) * D3];
                vr[j].z = src[(size_t)(k0 + 2) * D3];
                vr[j].w = src[(size_t)(k0 + 3) * D3];
            }
        }

        // ---- S = Q K^T  (16 q-rows x 64 keys per warp)
        const unsigned kb = sb + FA_K + st * 16384;
        float sf[8][4];
#pragma unroll
        for (int nf = 0; nf < 8; nf++)
#pragma unroll
            for (int j = 0; j < 4; j++) sf[nf][j] = 0.f;
#pragma unroll
        for (int ks = 0; ks < 8; ks++) {
            unsigned a[4];
            {
                int row = wid * 16 + rA;
                unsigned addr = sb + FA_Q + (unsigned)(row * 256 + (ks >> 2) * 128)
                              + (((unsigned)((ks & 3) * 32) + hiA) ^ ((unsigned)(row & 7) * 16));
                ldsm_x4(a, addr);
            }
            unsigned b[4][4];
#pragma unroll
            for (int nj = 0; nj < 4; nj++) {
                int row = nj * 16 + rB;
                unsigned addr = kb + (unsigned)(row * 256 + (ks >> 2) * 128)
                              + (((unsigned)((ks & 3) * 32) + hiB) ^ ((unsigned)(row & 7) * 16));
                ldsm_x4(b[nj], addr);
            }
#pragma unroll
            for (int nf = 0; nf < 8; nf++)
                mma_tf32(sf[nf], a, b[nf >> 1][(nf & 1) * 2], b[nf >> 1][(nf & 1) * 2 + 1]);
        }

        // ---- prefetch next K tile into the other stage
        if (kt < qb)
            tile_async(Kg + (size_t)(kt + 1) * 64 * D3, sb + FA_K + (st ^ 1) * 16384);
        CP_COMMIT();

        // ---- V STS (loads landed during S MMA): VsT[d][key], row stride 272B
#pragma unroll
        for (int j = 0; j < 8; j++) {
            int k0 = vkh * 32 + j * 4;
            *(float4*)(smc + FA_V + vd * 272 + k0 * 4) = vr[j];
        }

        // ---- online softmax on fragments (log2 domain)
        if (kt == qb) {
            int r0 = qbase + wid * 16 + g;
#pragma unroll
            for (int nf = 0; nf < 8; nf++) {
                int col = qbase + nf * 8 + qq * 2;
                if (col > r0)         sf[nf][0] = -1e30f;
                if (col + 1 > r0)     sf[nf][1] = -1e30f;
                if (col > r0 + 8)     sf[nf][2] = -1e30f;
                if (col + 1 > r0 + 8) sf[nf][3] = -1e30f;
            }
        }
        float t0 = -1e30f, t1 = -1e30f;
#pragma unroll
        for (int nf = 0; nf < 8; nf++) {
            t0 = fmaxf(t0, fmaxf(sf[nf][0], sf[nf][1]));
            t1 = fmaxf(t1, fmaxf(sf[nf][2], sf[nf][3]));
        }
        t0 = fmaxf(t0, __shfl_xor_sync(0xffffffffu, t0, 1));
        t0 = fmaxf(t0, __shfl_xor_sync(0xffffffffu, t0, 2));
        t1 = fmaxf(t1, __shfl_xor_sync(0xffffffffu, t1, 1));
        t1 = fmaxf(t1, __shfl_xor_sync(0xffffffffu, t1, 2));
        const float mn0 = fmaxf(m0, t0 * CST);
        const float mn1 = fmaxf(m1, t1 * CST);
        const float al0 = fast_exp2(m0 - mn0);
        const float al1 = fast_exp2(m1 - mn1);
        m0 = mn0; m1 = mn1;

        float ps0 = 0.f, ps1 = 0.f;
        const int pwo = FA_P + wid * 4096;
#pragma unroll
        for (int nf = 0; nf < 8; nf++) {
            float p00 = round_tf32(fast_exp2(fmaf(sf[nf][0], CST, -mn0)));
            float p01 = round_tf32(fast_exp2(fmaf(sf[nf][1], CST, -mn0)));
            float p10 = round_tf32(fast_exp2(fmaf(sf[nf][2], CST, -mn1)));
            float p11 = round_tf32(fast_exp2(fmaf(sf[nf][3], CST, -mn1)));
            ps0 += p00 + p01; ps1 += p10 + p11;
            unsigned offh = ((unsigned)((nf & 3) * 32 + qq * 8)) ^ ((unsigned)g * 16);
            int base = pwo + (nf >> 2) * 128 + (int)offh;
            *(float2*)(smc + base + g * 256)       = make_float2(p00, p01);
            *(float2*)(smc + base + (g + 8) * 256) = make_float2(p10, p11);
        }
        ps0 += __shfl_xor_sync(0xffffffffu, ps0, 1);
        ps0 += __shfl_xor_sync(0xffffffffu, ps0, 2);
        ps1 += __shfl_xor_sync(0xffffffffu, ps1, 1);
        ps1 += __shfl_xor_sync(0xffffffffu, ps1, 2);
        l0 = l0 * al0 + ps0;
        l1 = l1 * al1 + ps1;
#pragma unroll
        for (int nf = 0; nf < 8; nf++) {
            o[nf][0] *= al0; o[nf][1] *= al0;
            o[nf][2] *= al1; o[nf][3] *= al1;
        }
        __syncwarp();               // P visible within warp
        __syncthreads();            // VsT + P visible to all warps

        // ---- O += P * V  (P A-frags from smem, V^T B-frags)
#pragma unroll
        for (int ks = 0; ks < 8; ks++) {
            unsigned a[4];
            {
                int row = rA;
                unsigned addr = sb + (unsigned)(pwo + row * 256 + (ks >> 2) * 128)
                              + (((unsigned)((ks & 3) * 32) + hiA) ^ ((unsigned)(row & 7) * 16));
                ldsm_x4(a, addr);
            }
            unsigned b[4][4];
#pragma unroll
            for (int nj = 0; nj < 4; nj++) {
                int row = nj * 16 + rB;
                unsigned addr = sb + (unsigned)(FA_V + row * 272 + ks * 32) + hiB;
                ldsm_x4(b[nj], addr);
            }
#pragma unroll
            for (int nf = 0; nf < 8; nf++)
                mma_tf32(o[nf], a, b[nf >> 1][(nf & 1) * 2], b[nf >> 1][(nf & 1) * 2 + 1]);
        }
    }

    // ---- epilogue: normalize, tf32-round, store
    const float i0 = 1.f / l0, i1 = 1.f / l1;
    const int r0 = qbase + wid * 16 + g;
#pragma unroll
    for (int nf = 0; nf < 8; nf++) {
        int col = h * HD + nf * 8 + qq * 2;
        float2 v0 = make_float2(round_tf32(o[nf][0] * i0), round_tf32(o[nf][1] * i0));
        float2 v1 = make_float2(round_tf32(o[nf][2] * i1), round_tf32(o[nf][3] * i1));
        *(float2*)(attn + (size_t)r0 * D_EMBED + col)       = v0;
        *(float2*)(attn + (size_t)(r0 + 8) * D_EMBED + col) = v1;
    }
}

// ===========================================================================
extern "C" void kernel_launch(void* const* d_in, const int* in_sizes, int n_in,
                              void* d_out, int out_size)
{
    const float* hidden = (const float*)d_in[0];
    const float* w_qkv  = (const float*)d_in[1];
    const float* b_qkv  = (const float*)d_in[2];
    const float* w_out  = (const float*)d_in[3];
    const float* b_out  = (const float*)d_in[4];
    float* out = (float*)d_out;

    float *qkv, *attn, *hid_t, *wqkv_t, *wout_t;
    cudaGetSymbolAddress((void**)&qkv,    g_qkv);
    cudaGetSymbolAddress((void**)&attn,   g_attn);
    cudaGetSymbolAddress((void**)&hid_t,  g_hid_t);
    cudaGetSymbolAddress((void**)&wqkv_t, g_wqkv_t);
    cudaGetSymbolAddress((void**)&wout_t, g_wout_t);

    cudaFuncSetAttribute(gemm_tf32mma, cudaFuncAttributeMaxDynamicSharedMemorySize,
                         GEMM_SMEM_BYTES);
    cudaFuncSetAttribute(flash_attn_mma, cudaFuncAttributeMaxDynamicSharedMemorySize,
                         FA_SMEM);

    // RN-round GEMM inputs to tf32
    {
        int n4h = SEQ * D_EMBED / 4;
        round_tf32_kernel<<<(n4h + 255) / 256, 256>>>((const float4*)hidden, (float4*)hid_t, n4h);
        int n4w = D3 * D_EMBED / 4;
        round_tf32_kernel<<<(n4w + 255) / 256, 256>>>((const float4*)w_qkv, (float4*)wqkv_t, n4w);
        int n4o = D_EMBED * D_EMBED / 4;
        round_tf32_kernel<<<(n4o + 255) / 256, 256>>>((const float4*)w_out, (float4*)wout_t, n4o);
    }

    // 1) QKV projection (persistent tf32 mma.sync), output tf32-rounded
    gemm_tf32mma<<<GEMM_GRID, 256, GEMM_SMEM_BYTES>>>(
        hid_t, wqkv_t, b_qkv, qkv, D3, D_EMBED, SEQ, 1);

    // 2) Causal multi-head attention (tf32 mma.sync flash, LPT order)
    flash_attn_mma<<<dim3(SEQ / 64, NH), 128, FA_SMEM>>>(qkv, attn);

    // 3) Output projection (persistent tf32 mma.sync), full fp32 output
    gemm_tf32mma<<<GEMM_GRID, 256, GEMM_SMEM_BYTES>>>(
        attn, wout_t, b_out, out, D_EMBED, D_EMBED, SEQ, 0);
}